// round 1
// baseline (speedup 1.0000x reference)
#include <cuda_runtime.h>
#include <math.h>

#define Bn  32
#define LCn 2048
#define LRn 512
#define Dn  256
#define Hn  128
#define MC  (Bn * LCn)   // 65536 context rows
#define MR  (Bn * LRn)   // 16384 response rows
#define NCH 8            // column-softmax chunks

// -------- scratch (static device allocations; no cudaMalloc allowed) --------
static __device__ float g_E[(size_t)Bn * LCn * LRn];   // 134 MB score matrix
static __device__ float g_cd[(size_t)Bn * LCn * Dn];   // 67 MB
static __device__ float g_rd[(size_t)Bn * LRn * Dn];   // 17 MB
static __device__ float g_amax[MC], g_asum[MC];        // row softmax stats (alpha)
static __device__ float g_bmax[MR], g_bsum[MR];        // col softmax stats (beta)
static __device__ float g_pmax[Bn * NCH * LRn], g_psum[Bn * NCH * LRn];
static __device__ float g_W1c[Hn * 3 * Dn], g_W2c[Hn * 3 * Dn]; // folded weights

// ============================================================================
// Kernel 0: fold concat weights.
// out = cs*(Wa+Wc) + cd*(Wb-Wc) + (cs*cd)*Wd  (K: 1024 -> 768)
// ============================================================================
__global__ void k_wcomb(const float* __restrict__ W1, const float* __restrict__ W2) {
    int i = blockIdx.x * 256 + threadIdx.x;
    if (i >= Hn * Dn) return;
    int h = i >> 8, d = i & (Dn - 1);
    const float* w1 = W1 + (size_t)h * 4 * Dn;
    g_W1c[(size_t)h * 3 * Dn + d]          = w1[d] + w1[2 * Dn + d];
    g_W1c[(size_t)h * 3 * Dn + Dn + d]     = w1[Dn + d] - w1[2 * Dn + d];
    g_W1c[(size_t)h * 3 * Dn + 2 * Dn + d] = w1[3 * Dn + d];
    const float* w2 = W2 + (size_t)h * 4 * Dn;
    g_W2c[(size_t)h * 3 * Dn + d]          = w2[d] + w2[2 * Dn + d];
    g_W2c[(size_t)h * 3 * Dn + Dn + d]     = w2[Dn + d] - w2[2 * Dn + d];
    g_W2c[(size_t)h * 3 * Dn + 2 * Dn + d] = w2[3 * Dn + d];
}

// ============================================================================
// Kernel 1: E[b,c,r] = sum_d cs[b,c,d]*rs[b,r,d]   (NT sgemm, 64x64x16 tile)
// ============================================================================
__global__ void k_scores(const float* __restrict__ cs, const float* __restrict__ rs) {
    int b = blockIdx.z;
    const float* A  = cs + (size_t)b * LCn * Dn;
    const float* Bm = rs + (size_t)b * LRn * Dn;
    float* C = g_E + (size_t)b * LCn * LRn;
    __shared__ float As[16][65];
    __shared__ float Bs[16][65];
    int m0 = blockIdx.x * 64, n0 = blockIdx.y * 64;
    int tid = threadIdx.x;
    int tx = tid & 15, ty = tid >> 4;
    int lr = tid >> 2;            // 0..63 row of tile
    int lk = (tid & 3) << 2;      // 0,4,8,12 k quad
    float acc[4][4] = {};
    for (int k0 = 0; k0 < Dn; k0 += 16) {
        float4 va = *(const float4*)(A  + (size_t)(m0 + lr) * Dn + k0 + lk);
        float4 vb = *(const float4*)(Bm + (size_t)(n0 + lr) * Dn + k0 + lk);
        As[lk + 0][lr] = va.x; As[lk + 1][lr] = va.y; As[lk + 2][lr] = va.z; As[lk + 3][lr] = va.w;
        Bs[lk + 0][lr] = vb.x; Bs[lk + 1][lr] = vb.y; Bs[lk + 2][lr] = vb.z; Bs[lk + 3][lr] = vb.w;
        __syncthreads();
        #pragma unroll
        for (int k = 0; k < 16; k++) {
            float ra[4], rb[4];
            #pragma unroll
            for (int i = 0; i < 4; i++) ra[i] = As[k][ty * 4 + i];
            #pragma unroll
            for (int j = 0; j < 4; j++) rb[j] = Bs[k][tx * 4 + j];
            #pragma unroll
            for (int i = 0; i < 4; i++)
                #pragma unroll
                for (int j = 0; j < 4; j++)
                    acc[i][j] = fmaf(ra[i], rb[j], acc[i][j]);
        }
        __syncthreads();
    }
    #pragma unroll
    for (int i = 0; i < 4; i++) {
        float4 v = make_float4(acc[i][0], acc[i][1], acc[i][2], acc[i][3]);
        *(float4*)(C + (size_t)(m0 + ty * 4 + i) * LRn + n0 + tx * 4) = v;
    }
}

// ============================================================================
// Kernel 2: alpha row stats (softmax over r, one warp per row)
// ============================================================================
__global__ void k_alpha_stats() {
    int row  = blockIdx.x * 8 + (threadIdx.x >> 5);
    int lane = threadIdx.x & 31;
    const float* e = g_E + (size_t)row * LRn;
    float v[16], m = -1e30f;
    #pragma unroll
    for (int i = 0; i < 16; i++) { v[i] = e[lane + i * 32]; m = fmaxf(m, v[i]); }
    #pragma unroll
    for (int o = 16; o > 0; o >>= 1) m = fmaxf(m, __shfl_xor_sync(0xffffffffu, m, o));
    float s = 0.f;
    #pragma unroll
    for (int i = 0; i < 16; i++) s += __expf(v[i] - m);
    #pragma unroll
    for (int o = 16; o > 0; o >>= 1) s += __shfl_xor_sync(0xffffffffu, s, o);
    if (lane == 0) { g_amax[row] = m; g_asum[row] = s; }
}

// ============================================================================
// Kernel 3a/3b: beta column stats (softmax over c), chunked + online merge
// ============================================================================
__global__ void k_beta_part() {
    int b = blockIdx.z, ch = blockIdx.y;
    int r = blockIdx.x * 128 + threadIdx.x;
    const float* e = g_E + (size_t)b * LCn * LRn + r;
    int c0 = ch * (LCn / NCH);
    float m = -1e30f, s = 0.f;
    for (int c = 0; c < LCn / NCH; c += 4) {
        float v0 = e[(size_t)(c0 + c + 0) * LRn];
        float v1 = e[(size_t)(c0 + c + 1) * LRn];
        float v2 = e[(size_t)(c0 + c + 2) * LRn];
        float v3 = e[(size_t)(c0 + c + 3) * LRn];
        float nm = fmaxf(fmaxf(fmaxf(v0, v1), fmaxf(v2, v3)), m);
        s = s * __expf(m - nm) + __expf(v0 - nm) + __expf(v1 - nm)
                                + __expf(v2 - nm) + __expf(v3 - nm);
        m = nm;
    }
    int idx = (b * NCH + ch) * LRn + r;
    g_pmax[idx] = m; g_psum[idx] = s;
}

__global__ void k_beta_merge() {
    int idx = blockIdx.x * 256 + threadIdx.x;   // over MR
    int b = idx / LRn, r = idx % LRn;
    float m = -1e30f, s = 0.f;
    #pragma unroll
    for (int ch = 0; ch < NCH; ch++) {
        int p = (b * NCH + ch) * LRn + r;
        float pm = g_pmax[p], ps = g_psum[p];
        float nm = fmaxf(m, pm);
        s = s * __expf(m - nm) + ps * __expf(pm - nm);
        m = nm;
    }
    g_bmax[idx] = m; g_bsum[idx] = s;
}

// ============================================================================
// Kernel 4: cd[b,c,d] = (1/asum[c]) * sum_r exp(E[c,r]-amax[c]) * rs[r,d]  (NN)
// ============================================================================
__global__ void k_cd(const float* __restrict__ rs) {
    int b = blockIdx.z;
    const float* E  = g_E + (size_t)b * LCn * LRn;
    const float* Bm = rs + (size_t)b * LRn * Dn;
    float* C = g_cd + (size_t)b * LCn * Dn;
    __shared__ float As[16][65];
    __shared__ float Bs[16][65];
    int m0 = blockIdx.x * 64, n0 = blockIdx.y * 64;
    int tid = threadIdx.x, tx = tid & 15, ty = tid >> 4;
    int la_r = tid >> 2, la_k = (tid & 3) << 2;   // A: row, k-quad (transpose store)
    int lb_k = tid >> 4, lb_n = (tid & 15) << 2;  // B: k row, n-quad (direct store)
    float rmax = g_amax[b * LCn + m0 + la_r];
    float acc[4][4] = {};
    for (int k0 = 0; k0 < LRn; k0 += 16) {
        float4 va = *(const float4*)(E + (size_t)(m0 + la_r) * LRn + k0 + la_k);
        As[la_k + 0][la_r] = __expf(va.x - rmax);
        As[la_k + 1][la_r] = __expf(va.y - rmax);
        As[la_k + 2][la_r] = __expf(va.z - rmax);
        As[la_k + 3][la_r] = __expf(va.w - rmax);
        float4 vb = *(const float4*)(Bm + (size_t)(k0 + lb_k) * Dn + n0 + lb_n);
        Bs[lb_k][lb_n + 0] = vb.x; Bs[lb_k][lb_n + 1] = vb.y;
        Bs[lb_k][lb_n + 2] = vb.z; Bs[lb_k][lb_n + 3] = vb.w;
        __syncthreads();
        #pragma unroll
        for (int k = 0; k < 16; k++) {
            float ra[4], rb[4];
            #pragma unroll
            for (int i = 0; i < 4; i++) ra[i] = As[k][ty * 4 + i];
            #pragma unroll
            for (int j = 0; j < 4; j++) rb[j] = Bs[k][tx * 4 + j];
            #pragma unroll
            for (int i = 0; i < 4; i++)
                #pragma unroll
                for (int j = 0; j < 4; j++)
                    acc[i][j] = fmaf(ra[i], rb[j], acc[i][j]);
        }
        __syncthreads();
    }
    #pragma unroll
    for (int i = 0; i < 4; i++) {
        int m = m0 + ty * 4 + i;
        float inv = __frcp_rn(g_asum[b * LCn + m]);
        float4 v = make_float4(acc[i][0] * inv, acc[i][1] * inv, acc[i][2] * inv, acc[i][3] * inv);
        *(float4*)(C + (size_t)m * Dn + n0 + tx * 4) = v;
    }
}

// ============================================================================
// Kernel 5: rd[b,r,d] = (1/bsum[r]) * sum_c exp(E[c,r]-bmax[r]) * cs[c,d]  (TN)
// ============================================================================
__global__ void k_rd(const float* __restrict__ cs) {
    int b = blockIdx.z;
    const float* E  = g_E + (size_t)b * LCn * LRn;
    const float* Bm = cs + (size_t)b * LCn * Dn;
    float* C = g_rd + (size_t)b * LRn * Dn;
    __shared__ float As[16][65];
    __shared__ float Bs[16][65];
    __shared__ float cmaxs[64];
    int m0 = blockIdx.x * 64, n0 = blockIdx.y * 64;
    int tid = threadIdx.x, tx = tid & 15, ty = tid >> 4;
    int l_k = tid >> 4, l_m = (tid & 15) << 2;   // both loads: k row, quad along fast dim
    if (tid < 64) cmaxs[tid] = g_bmax[b * LRn + m0 + tid];
    __syncthreads();
    float acc[4][4] = {};
    for (int k0 = 0; k0 < LCn; k0 += 16) {
        float4 va = *(const float4*)(E + (size_t)(k0 + l_k) * LRn + m0 + l_m);
        As[l_k][l_m + 0] = __expf(va.x - cmaxs[l_m + 0]);
        As[l_k][l_m + 1] = __expf(va.y - cmaxs[l_m + 1]);
        As[l_k][l_m + 2] = __expf(va.z - cmaxs[l_m + 2]);
        As[l_k][l_m + 3] = __expf(va.w - cmaxs[l_m + 3]);
        float4 vb = *(const float4*)(Bm + (size_t)(k0 + l_k) * Dn + n0 + l_m);
        Bs[l_k][l_m + 0] = vb.x; Bs[l_k][l_m + 1] = vb.y;
        Bs[l_k][l_m + 2] = vb.z; Bs[l_k][l_m + 3] = vb.w;
        __syncthreads();
        #pragma unroll
        for (int k = 0; k < 16; k++) {
            float ra[4], rb[4];
            #pragma unroll
            for (int i = 0; i < 4; i++) ra[i] = As[k][ty * 4 + i];
            #pragma unroll
            for (int j = 0; j < 4; j++) rb[j] = Bs[k][tx * 4 + j];
            #pragma unroll
            for (int i = 0; i < 4; i++)
                #pragma unroll
                for (int j = 0; j < 4; j++)
                    acc[i][j] = fmaf(ra[i], rb[j], acc[i][j]);
        }
        __syncthreads();
    }
    #pragma unroll
    for (int i = 0; i < 4; i++) {
        int m = m0 + ty * 4 + i;
        float inv = __frcp_rn(g_bsum[b * LRn + m]);
        float4 v = make_float4(acc[i][0] * inv, acc[i][1] * inv, acc[i][2] * inv, acc[i][3] * inv);
        *(float4*)(C + (size_t)m * Dn + n0 + tx * 4) = v;
    }
}

// ============================================================================
// Kernel 6: fused FC: out = relu(X*Wa' + Y*Wb' + (X.*Y)*Wg' + bias)
//   which==0: X=cs(flat MC x D), Y=g_cd, W=g_W1c ; which==1: X=rs, Y=g_rd, W=g_W2c
// ============================================================================
__global__ void k_fc(const float* __restrict__ X, const float* __restrict__ bias,
                     float* __restrict__ out, int which) {
    const float* Y  = which ? g_rd  : g_cd;
    const float* Wc = which ? g_W2c : g_W1c;
    __shared__ float Xs[16][65], Ys[16][65];
    __shared__ float Wa[16][65], Wb[16][65], Wg[16][65];
    int m0 = blockIdx.x * 64, n0 = blockIdx.y * 64;
    int tid = threadIdx.x, tx = tid & 15, ty = tid >> 4;
    int lr = tid >> 2, lk = (tid & 3) << 2;
    float acc[4][4] = {};
    for (int d0 = 0; d0 < Dn; d0 += 16) {
        float4 vx = *(const float4*)(X + (size_t)(m0 + lr) * Dn + d0 + lk);
        float4 vy = *(const float4*)(Y + (size_t)(m0 + lr) * Dn + d0 + lk);
        Xs[lk + 0][lr] = vx.x; Xs[lk + 1][lr] = vx.y; Xs[lk + 2][lr] = vx.z; Xs[lk + 3][lr] = vx.w;
        Ys[lk + 0][lr] = vy.x; Ys[lk + 1][lr] = vy.y; Ys[lk + 2][lr] = vy.z; Ys[lk + 3][lr] = vy.w;
        const float* wrow = Wc + (size_t)(n0 + lr) * (3 * Dn) + d0 + lk;
        float4 wa = *(const float4*)(wrow);
        float4 wb = *(const float4*)(wrow + Dn);
        float4 wg = *(const float4*)(wrow + 2 * Dn);
        Wa[lk + 0][lr] = wa.x; Wa[lk + 1][lr] = wa.y; Wa[lk + 2][lr] = wa.z; Wa[lk + 3][lr] = wa.w;
        Wb[lk + 0][lr] = wb.x; Wb[lk + 1][lr] = wb.y; Wb[lk + 2][lr] = wb.z; Wb[lk + 3][lr] = wb.w;
        Wg[lk + 0][lr] = wg.x; Wg[lk + 1][lr] = wg.y; Wg[lk + 2][lr] = wg.z; Wg[lk + 3][lr] = wg.w;
        __syncthreads();
        #pragma unroll
        for (int k = 0; k < 16; k++) {
            float rx[4], ry[4], gg[4], wav[4], wbv[4], wgv[4];
            #pragma unroll
            for (int i = 0; i < 4; i++) {
                rx[i] = Xs[k][ty * 4 + i];
                ry[i] = Ys[k][ty * 4 + i];
                gg[i] = rx[i] * ry[i];
            }
            #pragma unroll
            for (int j = 0; j < 4; j++) {
                wav[j] = Wa[k][tx * 4 + j];
                wbv[j] = Wb[k][tx * 4 + j];
                wgv[j] = Wg[k][tx * 4 + j];
            }
            #pragma unroll
            for (int i = 0; i < 4; i++)
                #pragma unroll
                for (int j = 0; j < 4; j++)
                    acc[i][j] = fmaf(gg[i], wgv[j],
                                fmaf(ry[i], wbv[j],
                                fmaf(rx[i], wav[j], acc[i][j])));
        }
        __syncthreads();
    }
    #pragma unroll
    for (int i = 0; i < 4; i++) {
        int m = m0 + ty * 4 + i;
        float o0 = fmaxf(acc[i][0] + bias[n0 + tx * 4 + 0], 0.f);
        float o1 = fmaxf(acc[i][1] + bias[n0 + tx * 4 + 1], 0.f);
        float o2 = fmaxf(acc[i][2] + bias[n0 + tx * 4 + 2], 0.f);
        float o3 = fmaxf(acc[i][3] + bias[n0 + tx * 4 + 3], 0.f);
        *(float4*)(out + (size_t)m * Hn + n0 + tx * 4) = make_float4(o0, o1, o2, o3);
    }
}

// ============================================================================
extern "C" void kernel_launch(void* const* d_in, const int* in_sizes, int n_in,
                              void* d_out, int out_size) {
    const float* cs = (const float*)d_in[0];
    const float* rs = (const float*)d_in[1];
    const float* W1 = (const float*)d_in[2];
    const float* b1 = (const float*)d_in[3];
    const float* W2 = (const float*)d_in[4];
    const float* b2 = (const float*)d_in[5];
    float* cl = (float*)d_out;
    float* rl = cl + (size_t)MC * Hn;

    k_wcomb<<<(Hn * Dn + 255) / 256, 256>>>(W1, W2);
    k_scores<<<dim3(LCn / 64, LRn / 64, Bn), 256>>>(cs, rs);
    k_alpha_stats<<<MC / 8, 256>>>();
    k_beta_part<<<dim3(LRn / 128, NCH, Bn), 128>>>();
    k_beta_merge<<<MR / 256, 256>>>();
    k_cd<<<dim3(LCn / 64, Dn / 64, Bn), 256>>>(rs);
    k_rd<<<dim3(LRn / 64, Dn / 64, Bn), 256>>>(cs);
    k_fc<<<dim3(MC / 64, Hn / 64), 256>>>(cs, b1, cl, 0);
    k_fc<<<dim3(MR / 64, Hn / 64), 256>>>(rs, b2, rl, 1);
}

// round 3
// speedup vs baseline: 2.3606x; 2.3606x over previous
#include <cuda_runtime.h>
#include <cuda_bf16.h>
#include <math.h>
#include <stdint.h>

#define Bn  32
#define LCn 2048
#define LRn 512
#define Dn  256
#define Hn  128
#define MC  (Bn * LCn)
#define MR  (Bn * LRn)
#define NCH 8

// -------- scratch --------
static __device__ float g_E [(size_t)Bn * LCn * LRn];
static __device__ float g_ET[(size_t)Bn * LRn * LCn];
static __device__ float g_cd[(size_t)Bn * LCn * Dn];
static __device__ float g_rd[(size_t)Bn * LRn * Dn];
static __device__ float g_rsT[(size_t)Bn * Dn * LRn];
static __device__ float g_csT[(size_t)Bn * Dn * LCn];
static __device__ float g_amax[MC], g_asum[MC];
static __device__ float g_bmax[MR], g_bsum[MR];
static __device__ float g_pmax[Bn * NCH * LRn], g_psum[Bn * NCH * LRn];
static __device__ float g_W1c[Hn * 3 * Dn], g_W2c[Hn * 3 * Dn];

// ======================== helpers =============================
__device__ __forceinline__ uint32_t smem_u32(const void* p) {
    uint32_t a;
    asm("{ .reg .u64 t; cvta.to.shared.u64 t, %1; cvt.u32.u64 %0, t; }" : "=r"(a) : "l"(p));
    return a;
}

#define LDSM4(r, addr) \
    asm volatile("ldmatrix.sync.aligned.m8n8.x4.shared.b16 {%0,%1,%2,%3}, [%4];" \
        : "=r"((r)[0]), "=r"((r)[1]), "=r"((r)[2]), "=r"((r)[3]) : "r"(addr))

#define MMA_BF16(c, a, b0, b1) \
    asm volatile("mma.sync.aligned.m16n8k16.row.col.f32.bf16.bf16.f32 " \
        "{%0,%1,%2,%3}, {%4,%5,%6,%7}, {%8,%9}, {%0,%1,%2,%3};" \
        : "+f"((c)[0]), "+f"((c)[1]), "+f"((c)[2]), "+f"((c)[3]) \
        : "r"((a)[0]), "r"((a)[1]), "r"((a)[2]), "r"((a)[3]), "r"(b0), "r"(b1))

#define STS64(addr, v0, v1) \
    asm volatile("st.shared.v2.b32 [%0], {%1,%2};" :: "r"(addr), "r"(v0), "r"(v1) : "memory")

__device__ __forceinline__ void bsplit(float v, uint16_t& h, uint16_t& l) {
    __nv_bfloat16 hb = __float2bfloat16(v);
    h = __bfloat16_as_ushort(hb);
    l = __bfloat16_as_ushort(__float2bfloat16(v - __bfloat162float(hb)));
}

// smem tile layout: [128 rows][32 k] bf16, row = 64B = 4x16B units,
// unit swizzle: c16' = c16 ^ (row & 3)
__device__ __forceinline__ uint32_t toff(int row, int c16) {
    return (row << 6) + ((c16 ^ (row & 3)) << 4);
}

#define TILE_BYTES 8192
#define SM_AH 0
#define SM_AL 8192
#define SM_BH 16384
#define SM_BL 24576

// ============================================================================
// Unified NT tensor-core GEMM: C[128,128] = A[128,K] * B[128,K]^T (bf16x3)
// MODE 0: plain.  MODE 1: A=exp(A-rmax[row]); epi *= 1/rsum[row].
// MODE 2: A = [X | Y | X*Y] (K=3*Dn); epi = relu(+bias).
// ============================================================================
template<int MODE>
__global__ void __launch_bounds__(256, 1) k_gemm(
    const float* __restrict__ Ap, const float* __restrict__ Bp,
    const float* __restrict__ Xp, const float* __restrict__ Yp,
    const float* __restrict__ rmax, const float* __restrict__ rsum,
    const float* __restrict__ bias, float* __restrict__ Cp,
    int K, int lda, int ldb, int ldc,
    size_t aB, size_t bB, size_t cB, int sB)
{
    __shared__ __align__(16) uint8_t sm[4 * TILE_BYTES];
    const uint32_t sb = smem_u32(sm);
    const int tid = threadIdx.x;
    const int z = blockIdx.z;
    const int m0 = blockIdx.x * 128, n0 = blockIdx.y * 128;
    const float* A  = Ap + (size_t)z * aB;
    const float* Bm = Bp + (size_t)z * bB;
    float* C = Cp + (size_t)z * cB;

    const int lane = tid & 31, wid = tid >> 5;
    const int wm = wid & 3, wn = wid >> 2;        // 4x2 warps: 32 rows x 64 cols
    const int gid = lane >> 2, tig = lane & 3;

    // fill mapping: idx = tid + i*256 -> row = idx>>3 (0..127), k4 = idx&7
    const int frow = tid >> 3, fk4 = tid & 7;

    float acc[2][8][4];
    #pragma unroll
    for (int a = 0; a < 2; a++)
        #pragma unroll
        for (int b = 0; b < 8; b++)
            #pragma unroll
            for (int c = 0; c < 4; c++) acc[a][b][c] = 0.f;

    const int S = K >> 5;
    float4 pa[4], pb[4];

    // ---- prefetch chunk 0 ----
    {
        const int k0 = 0;
        #pragma unroll
        for (int i = 0; i < 4; i++) {
            int row = frow + i * 32;
            int kk = k0 + (fk4 << 2);
            if (MODE == 2) {
                float4 x = *(const float4*)(Xp + (size_t)(m0 + row) * Dn + kk);
                pa[i] = x;     // seg 0
            } else {
                pa[i] = *(const float4*)(A + (size_t)(m0 + row) * lda + kk);
            }
            pb[i] = *(const float4*)(Bm + (size_t)(n0 + row) * ldb + kk);
        }
    }

    for (int s = 0; s < S; s++) {
        const int k0 = s << 5;
        // ---- convert + STS ----
        #pragma unroll
        for (int i = 0; i < 4; i++) {
            int row = frow + i * 32;
            float4 v = pa[i];
            if (MODE == 1) {
                float rm = __ldg(rmax + (size_t)z * sB + m0 + row);
                v.x = __expf(v.x - rm); v.y = __expf(v.y - rm);
                v.z = __expf(v.z - rm); v.w = __expf(v.w - rm);
            }
            uint16_t h0,h1,h2,h3,l0,l1,l2,l3;
            bsplit(v.x,h0,l0); bsplit(v.y,h1,l1); bsplit(v.z,h2,l2); bsplit(v.w,h3,l3);
            uint32_t off = toff(row, fk4 >> 1) + ((fk4 & 1) << 3);
            STS64(sb + SM_AH + off, (uint32_t)h0 | ((uint32_t)h1 << 16),
                                    (uint32_t)h2 | ((uint32_t)h3 << 16));
            STS64(sb + SM_AL + off, (uint32_t)l0 | ((uint32_t)l1 << 16),
                                    (uint32_t)l2 | ((uint32_t)l3 << 16));
            float4 w = pb[i];
            bsplit(w.x,h0,l0); bsplit(w.y,h1,l1); bsplit(w.z,h2,l2); bsplit(w.w,h3,l3);
            STS64(sb + SM_BH + off, (uint32_t)h0 | ((uint32_t)h1 << 16),
                                    (uint32_t)h2 | ((uint32_t)h3 << 16));
            STS64(sb + SM_BL + off, (uint32_t)l0 | ((uint32_t)l1 << 16),
                                    (uint32_t)l2 | ((uint32_t)l3 << 16));
        }
        __syncthreads();

        // ---- prefetch next chunk ----
        if (s + 1 < S) {
            const int kn = k0 + 32;
            #pragma unroll
            for (int i = 0; i < 4; i++) {
                int row = frow + i * 32;
                int kk = kn + (fk4 << 2);
                if (MODE == 2) {
                    int seg = kn >> 8;
                    int d = (kn & 255) + (fk4 << 2);
                    float4 x = *(const float4*)(Xp + (size_t)(m0 + row) * Dn + d);
                    if (seg == 0) pa[i] = x;
                    else {
                        float4 y = *(const float4*)(Yp + (size_t)(m0 + row) * Dn + d);
                        if (seg == 1) pa[i] = y;
                        else pa[i] = make_float4(x.x*y.x, x.y*y.y, x.z*y.z, x.w*y.w);
                    }
                } else {
                    pa[i] = *(const float4*)(A + (size_t)(m0 + row) * lda + kk);
                }
                pb[i] = *(const float4*)(Bm + (size_t)(n0 + row) * ldb + kk);
            }
        }

        // ---- compute 2 x k16 steps ----
        #pragma unroll
        for (int kb = 0; kb < 2; kb++) {
            // A fragments: lane L -> row = base + (L&15), c16 = kb*2 + (L>>4)
            uint32_t ah[2][4], al[2][4];
            #pragma unroll
            for (int mb = 0; mb < 2; mb++) {
                int row = wm * 32 + mb * 16 + (lane & 15);
                uint32_t off = toff(row, kb * 2 + (lane >> 4));
                LDSM4(ah[mb], sb + SM_AH + off);
                LDSM4(al[mb], sb + SM_AL + off);
            }
            #pragma unroll
            for (int np = 0; np < 4; np++) {
                // B: lanes0-7 n0-7/k0-7, 8-15 n0-7/k8-15, 16-23 n8-15/k0-7, 24-31 n8-15/k8-15
                int nrow = wn * 64 + np * 16 + (lane & 7) + ((lane >> 4) << 3);
                uint32_t off = toff(nrow, kb * 2 + ((lane >> 3) & 1));
                uint32_t bh[4], bl[4];
                LDSM4(bh, sb + SM_BH + off);
                LDSM4(bl, sb + SM_BL + off);
                #pragma unroll
                for (int nb = 0; nb < 2; nb++) {
                    int n = np * 2 + nb;
                    #pragma unroll
                    for (int mb = 0; mb < 2; mb++) {
                        MMA_BF16(acc[mb][n], ah[mb], bh[nb*2], bh[nb*2+1]);
                        MMA_BF16(acc[mb][n], ah[mb], bl[nb*2], bl[nb*2+1]);
                        MMA_BF16(acc[mb][n], al[mb], bh[nb*2], bh[nb*2+1]);
                    }
                }
            }
        }
        __syncthreads();
    }

    // ---- epilogue ----
    #pragma unroll
    for (int mb = 0; mb < 2; mb++) {
        int r0 = m0 + wm * 32 + mb * 16 + gid;
        int r1 = r0 + 8;
        float s0 = 1.f, s1 = 1.f;
        if (MODE == 1) {
            s0 = 1.0f / rsum[(size_t)z * sB + r0];
            s1 = 1.0f / rsum[(size_t)z * sB + r1];
        }
        #pragma unroll
        for (int nb = 0; nb < 8; nb++) {
            int col = n0 + wn * 64 + nb * 8 + tig * 2;
            float c0 = acc[mb][nb][0], c1 = acc[mb][nb][1];
            float c2 = acc[mb][nb][2], c3 = acc[mb][nb][3];
            if (MODE == 1) { c0 *= s0; c1 *= s0; c2 *= s1; c3 *= s1; }
            if (MODE == 2) {
                float b0v = bias[col], b1v = bias[col + 1];
                c0 = fmaxf(c0 + b0v, 0.f); c1 = fmaxf(c1 + b1v, 0.f);
                c2 = fmaxf(c2 + b0v, 0.f); c3 = fmaxf(c3 + b1v, 0.f);
            }
            *(float2*)(C + (size_t)r0 * ldc + col) = make_float2(c0, c1);
            *(float2*)(C + (size_t)r1 * ldc + col) = make_float2(c2, c3);
        }
    }
}

// ============================================================================
// Batched 32x32 transpose
// ============================================================================
__global__ void k_transpose(const float* __restrict__ src, float* __restrict__ dst,
                            int rows, int cols) {
    __shared__ float t[32][33];
    int b = blockIdx.z;
    src += (size_t)b * rows * cols;
    dst += (size_t)b * rows * cols;
    int c0 = blockIdx.x * 32, r0 = blockIdx.y * 32;
    int x = threadIdx.x, y = threadIdx.y;
    #pragma unroll
    for (int i = 0; i < 32; i += 8)
        t[y + i][x] = src[(size_t)(r0 + y + i) * cols + c0 + x];
    __syncthreads();
    #pragma unroll
    for (int i = 0; i < 32; i += 8)
        dst[(size_t)(c0 + y + i) * rows + r0 + x] = t[x][y + i];
}

// ============================================================================
// Weight folding + softmax stats
// ============================================================================
__global__ void k_wcomb(const float* __restrict__ W1, const float* __restrict__ W2) {
    int i = blockIdx.x * 256 + threadIdx.x;
    if (i >= Hn * Dn) return;
    int h = i >> 8, d = i & (Dn - 1);
    const float* w1 = W1 + (size_t)h * 4 * Dn;
    g_W1c[(size_t)h * 3 * Dn + d]          = w1[d] + w1[2 * Dn + d];
    g_W1c[(size_t)h * 3 * Dn + Dn + d]     = w1[Dn + d] - w1[2 * Dn + d];
    g_W1c[(size_t)h * 3 * Dn + 2 * Dn + d] = w1[3 * Dn + d];
    const float* w2 = W2 + (size_t)h * 4 * Dn;
    g_W2c[(size_t)h * 3 * Dn + d]          = w2[d] + w2[2 * Dn + d];
    g_W2c[(size_t)h * 3 * Dn + Dn + d]     = w2[Dn + d] - w2[2 * Dn + d];
    g_W2c[(size_t)h * 3 * Dn + 2 * Dn + d] = w2[3 * Dn + d];
}

__global__ void k_alpha_stats() {
    int row  = blockIdx.x * 8 + (threadIdx.x >> 5);
    int lane = threadIdx.x & 31;
    const float* e = g_E + (size_t)row * LRn;
    float v[16], m = -1e30f;
    #pragma unroll
    for (int i = 0; i < 16; i++) { v[i] = e[lane + i * 32]; m = fmaxf(m, v[i]); }
    #pragma unroll
    for (int o = 16; o > 0; o >>= 1) m = fmaxf(m, __shfl_xor_sync(0xffffffffu, m, o));
    float s = 0.f;
    #pragma unroll
    for (int i = 0; i < 16; i++) s += __expf(v[i] - m);
    #pragma unroll
    for (int o = 16; o > 0; o >>= 1) s += __shfl_xor_sync(0xffffffffu, s, o);
    if (lane == 0) { g_amax[row] = m; g_asum[row] = s; }
}

__global__ void k_beta_part() {
    int b = blockIdx.z, ch = blockIdx.y;
    int r = blockIdx.x * 128 + threadIdx.x;
    const float* e = g_E + (size_t)b * LCn * LRn + r;
    int c0 = ch * (LCn / NCH);
    float m = -1e30f, s = 0.f;
    for (int c = 0; c < LCn / NCH; c += 4) {
        float v0 = e[(size_t)(c0 + c + 0) * LRn];
        float v1 = e[(size_t)(c0 + c + 1) * LRn];
        float v2 = e[(size_t)(c0 + c + 2) * LRn];
        float v3 = e[(size_t)(c0 + c + 3) * LRn];
        float nm = fmaxf(fmaxf(fmaxf(v0, v1), fmaxf(v2, v3)), m);
        s = s * __expf(m - nm) + __expf(v0 - nm) + __expf(v1 - nm)
                                + __expf(v2 - nm) + __expf(v3 - nm);
        m = nm;
    }
    int idx = (b * NCH + ch) * LRn + r;
    g_pmax[idx] = m; g_psum[idx] = s;
}

__global__ void k_beta_merge() {
    int idx = blockIdx.x * 256 + threadIdx.x;
    int b = idx / LRn, r = idx % LRn;
    float m = -1e30f, s = 0.f;
    #pragma unroll
    for (int ch = 0; ch < NCH; ch++) {
        int p = (b * NCH + ch) * LRn + r;
        float pm = g_pmax[p], ps = g_psum[p];
        float nm = fmaxf(m, pm);
        s = s * __expf(m - nm) + ps * __expf(pm - nm);
        m = nm;
    }
    g_bmax[idx] = m; g_bsum[idx] = s;
}

// ============================================================================
extern "C" void kernel_launch(void* const* d_in, const int* in_sizes, int n_in,
                              void* d_out, int out_size) {
    const float* cs = (const float*)d_in[0];
    const float* rs = (const float*)d_in[1];
    const float* W1 = (const float*)d_in[2];
    const float* b1 = (const float*)d_in[3];
    const float* W2 = (const float*)d_in[4];
    const float* b2 = (const float*)d_in[5];
    float* cl = (float*)d_out;
    float* rl = cl + (size_t)MC * Hn;

    float* gE;  cudaGetSymbolAddress((void**)&gE,  g_E);
    float* gET; cudaGetSymbolAddress((void**)&gET, g_ET);
    float* gcd; cudaGetSymbolAddress((void**)&gcd, g_cd);
    float* grd; cudaGetSymbolAddress((void**)&grd, g_rd);
    float* grsT; cudaGetSymbolAddress((void**)&grsT, g_rsT);
    float* gcsT; cudaGetSymbolAddress((void**)&gcsT, g_csT);
    float* gam; cudaGetSymbolAddress((void**)&gam, g_amax);
    float* gas; cudaGetSymbolAddress((void**)&gas, g_asum);
    float* gbm; cudaGetSymbolAddress((void**)&gbm, g_bmax);
    float* gbs; cudaGetSymbolAddress((void**)&gbs, g_bsum);
    float* gw1; cudaGetSymbolAddress((void**)&gw1, g_W1c);
    float* gw2; cudaGetSymbolAddress((void**)&gw2, g_W2c);

    k_wcomb<<<(Hn * Dn + 255) / 256, 256>>>(W1, W2);
    k_transpose<<<dim3(8, 16, Bn), dim3(32, 8)>>>(rs, grsT, LRn, Dn);
    k_transpose<<<dim3(8, 64, Bn), dim3(32, 8)>>>(cs, gcsT, LCn, Dn);

    // E = cs * rs^T
    k_gemm<0><<<dim3(16, 4, Bn), 256>>>(
        cs, rs, nullptr, nullptr, nullptr, nullptr, nullptr, gE,
        Dn, Dn, Dn, LRn,
        (size_t)LCn * Dn, (size_t)LRn * Dn, (size_t)LCn * LRn, 0);

    k_alpha_stats<<<MC / 8, 256>>>();
    k_beta_part<<<dim3(LRn / 128, NCH, Bn), 128>>>();
    k_beta_merge<<<MR / 256, 256>>>();
    k_transpose<<<dim3(16, 64, Bn), dim3(32, 8)>>>(gE, gET, LCn, LRn);

    // cd = softmax_r(E) * rs       (A = E rows + exp, B = rs^T)
    k_gemm<1><<<dim3(16, 2, Bn), 256>>>(
        gE, grsT, nullptr, nullptr, gam, gas, nullptr, gcd,
        LRn, LRn, LRn, Dn,
        (size_t)LCn * LRn, (size_t)Dn * LRn, (size_t)LCn * Dn, LCn);

    // rd = softmax_c(E)^T * cs     (A = E^T rows + exp, B = cs^T)
    k_gemm<1><<<dim3(4, 2, Bn), 256>>>(
        gET, gcsT, nullptr, nullptr, gbm, gbs, nullptr, grd,
        LCn, LCn, LCn, Dn,
        (size_t)LRn * LCn, (size_t)Dn * LCn, (size_t)LRn * Dn, LRn);

    // cl = relu([cs|cd|cs*cd] * W1c^T + b1)
    k_gemm<2><<<dim3(MC / 128, 1, 1), 256>>>(
        nullptr, gw1, cs, gcd, nullptr, nullptr, b1, cl,
        3 * Dn, 0, 3 * Dn, Hn, 0, 0, 0, 0);

    // rl = relu([rs|rd|rs*rd] * W2c^T + b2)
    k_gemm<2><<<dim3(MR / 128, 1, 1), 256>>>(
        nullptr, gw2, rs, grd, nullptr, nullptr, b2, rl,
        3 * Dn, 0, 3 * Dn, Hn, 0, 0, 0, 0);
}